// round 10
// baseline (speedup 1.0000x reference)
#include <cuda_runtime.h>
#include <cuda_fp16.h>
#include <cstdint>

// WQuantLinear factorized:
//   q = clip(round(w*(1/scale))+zero, 0, 15)   (exact small int in fp16)
//   out = scale[n]*(sum_k h(a)*q) - scale[n]*zero[n]*S[m] + bias[n],  S[m]=sum_k h(a)
// prep: A->fp16 + rowsums, W->fp16 integer q. GEMM: fp16 HMMA m16n8k16, fp32 accum,
// 256 threads/CTA (8 warps, 32x32 warp tiles). R9 fix: exact tail wait_group counts
// (tiles <= kt+1 must be resident; allowed outstanding = 1 only while kt+3 <= NT).

constexpr int M_TOTAL = 256;
constexpr int N_TOTAL = 11008;
constexpr int K_TOTAL = 4096;

constexpr int BM = 128;
constexpr int BN = 64;
constexpr int BK = 32;
constexpr int NT = K_TOTAL / BK;       // 128
constexpr int GEMM_THREADS = 256;      // 8 warps: 4(m) x 2(n), 32x32 warp tiles
constexpr int STAGES = 4;

constexpr int ROW_B = 80;              // 64B data + 16B pad (conflict-free LDSM)
constexpr int A_STAGE_B = BM * ROW_B;          // 10240
constexpr int B_STAGE_B = BN * ROW_B;          // 5120
constexpr int STAGE_B = A_STAGE_B + B_STAGE_B; // 15360
constexpr int SMEM_BYTES = STAGES * STAGE_B;   // 61440

// ---- device scratch ----
__device__ __half g_Ah[M_TOTAL * K_TOTAL];
__device__ float  g_S[M_TOTAL];
__device__ __half g_Qh[(size_t)N_TOTAL * K_TOTAL];   // 90MB fp16 integer q

__device__ __forceinline__ void mma_f16(float c[4], const uint32_t a[4], const uint32_t b[2]) {
    asm volatile(
        "mma.sync.aligned.m16n8k16.row.col.f32.f16.f16.f32 "
        "{%0,%1,%2,%3}, {%4,%5,%6,%7}, {%8,%9}, {%0,%1,%2,%3};"
        : "+f"(c[0]), "+f"(c[1]), "+f"(c[2]), "+f"(c[3])
        : "r"(a[0]), "r"(a[1]), "r"(a[2]), "r"(a[3]), "r"(b[0]), "r"(b[1]));
}
__device__ __forceinline__ void ldsm4(uint32_t r[4], uint32_t addr) {
    asm volatile("ldmatrix.sync.aligned.m8n8.x4.shared.b16 {%0,%1,%2,%3}, [%4];"
                 : "=r"(r[0]), "=r"(r[1]), "=r"(r[2]), "=r"(r[3]) : "r"(addr));
}
__device__ __forceinline__ void cpasync16(uint32_t dst, const void* src) {
    asm volatile("cp.async.cg.shared.global [%0], [%1], 16;" :: "r"(dst), "l"(src) : "memory");
}
__device__ __forceinline__ uint32_t s2u(const void* p) {
    uint32_t a;
    asm("{ .reg .u64 t; cvta.to.shared.u64 t, %1; cvt.u32.u64 %0, t; }" : "=r"(a) : "l"(p));
    return a;
}

// ---------------- fused prep ----------------
__global__ __launch_bounds__(128) void prep_kernel(const float* __restrict__ A,
                                                   const float* __restrict__ W,
                                                   const float* __restrict__ scale,
                                                   const float* __restrict__ zero) {
    const int tid = threadIdx.x;
    if (blockIdx.x < (unsigned)N_TOTAL) {
        const int row = blockIdx.x;
        const float s = scale[row];
        const float z = zero[row];
        const float r = __fdiv_rn(1.0f, s);
        const float* src = W + (size_t)row * K_TOTAL;
        __half* dst = g_Qh + (size_t)row * K_TOTAL;
#pragma unroll
        for (int i = 0; i < K_TOTAL / (128 * 4); i++) {
            float4 v = *(const float4*)(src + (i * 128 + tid) * 4);
            float q0 = fminf(fmaxf(rintf(__fmul_rn(v.x, r)) + z, 0.0f), 15.0f);
            float q1 = fminf(fmaxf(rintf(__fmul_rn(v.y, r)) + z, 0.0f), 15.0f);
            float q2 = fminf(fmaxf(rintf(__fmul_rn(v.z, r)) + z, 0.0f), 15.0f);
            float q3 = fminf(fmaxf(rintf(__fmul_rn(v.w, r)) + z, 0.0f), 15.0f);
            __half2 p0 = __halves2half2(__float2half_rn(q0), __float2half_rn(q1));
            __half2 p1 = __halves2half2(__float2half_rn(q2), __float2half_rn(q3));
            *(uint2*)(dst + (i * 128 + tid) * 4) =
                make_uint2(*(uint32_t*)&p0, *(uint32_t*)&p1);
        }
    } else {
        const int row = blockIdx.x - N_TOTAL;
        const float* src = A + (size_t)row * K_TOTAL;
        __half* dst = g_Ah + (size_t)row * K_TOTAL;
        float s = 0.0f;
#pragma unroll
        for (int i = 0; i < K_TOTAL / (128 * 4); i++) {
            float4 v = *(const float4*)(src + (i * 128 + tid) * 4);
            __half h0 = __float2half_rn(v.x), h1 = __float2half_rn(v.y);
            __half h2 = __float2half_rn(v.z), h3 = __float2half_rn(v.w);
            __half2 p0 = __halves2half2(h0, h1), p1 = __halves2half2(h2, h3);
            *(uint2*)(dst + (i * 128 + tid) * 4) =
                make_uint2(*(uint32_t*)&p0, *(uint32_t*)&p1);
            s += __half2float(h0) + __half2float(h1) + __half2float(h2) + __half2float(h3);
        }
#pragma unroll
        for (int o = 16; o > 0; o >>= 1) s += __shfl_xor_sync(0xffffffffu, s, o);
        __shared__ float ws[4];
        if ((tid & 31) == 0) ws[tid >> 5] = s;
        __syncthreads();
        if (tid == 0) g_S[row] = ws[0] + ws[1] + ws[2] + ws[3];
    }
}

// ---------------- GEMM ----------------
__global__ __launch_bounds__(GEMM_THREADS, 2)
void wq_gemm_kernel(const float* __restrict__ bias,
                    const float* __restrict__ scale,
                    const float* __restrict__ zero,
                    float* __restrict__ out)
{
    extern __shared__ char smem[];
    const uint32_t sb = s2u(smem);
    const int tid  = threadIdx.x;
    const int wid  = tid >> 5;
    const int lane = tid & 31;
    const int gid  = lane >> 2;
    const int tig  = lane & 3;
    const int wm   = wid & 3;        // 4 m-slabs of 32
    const int wn   = wid >> 2;       // 2 n-slabs of 32
    const int bn0 = blockIdx.x * BN;
    const int bm0 = blockIdx.y * BM;

    const __half* gA = g_Ah + (size_t)bm0 * K_TOTAL;
    const __half* gQ = g_Qh + (size_t)bn0 * K_TOTAL;

    const int st_row = tid >> 2;     // 0..63
    const int st_c16 = tid & 3;

    auto stage_tile = [&](int kt) {
        const int s = kt & (STAGES - 1);
        const uint32_t as = sb + s * STAGE_B;
        const uint32_t bs = as + A_STAGE_B;
        const int k0 = kt * BK;
#pragma unroll
        for (int j = 0; j < 2; j++) {
            const int row = st_row + 64 * j;
            cpasync16(as + row * ROW_B + st_c16 * 16,
                      gA + (size_t)row * K_TOTAL + k0 + st_c16 * 8);
        }
        cpasync16(bs + st_row * ROW_B + st_c16 * 16,
                  gQ + (size_t)st_row * K_TOTAL + k0 + st_c16 * 8);
        asm volatile("cp.async.commit_group;" ::: "memory");
    };

    stage_tile(0);
    stage_tile(1);
    stage_tile(2);

    const uint32_t a_frag = (uint32_t)((wm * 32 + (lane & 15)) * ROW_B + (lane >> 4) * 16);
    const uint32_t b_frag = (uint32_t)((wn * 32 + (lane & 7) + ((lane & 16) ? 8 : 0)) * ROW_B
                                       + ((lane & 8) ? 16 : 0));

    float acc[2][4][4];
#pragma unroll
    for (int mt = 0; mt < 2; mt++)
#pragma unroll
        for (int nt = 0; nt < 4; nt++)
#pragma unroll
            for (int i = 0; i < 4; i++) acc[mt][nt][i] = 0.0f;

    uint32_t af[2][2][4];
    uint32_t bf[2][2][4];

    asm volatile("cp.async.wait_group 2;" ::: "memory");
    __syncthreads();
    {
        const uint32_t as = sb, bs = sb + A_STAGE_B;
#pragma unroll
        for (int mt = 0; mt < 2; mt++) ldsm4(af[0][mt], as + a_frag + mt * (16 * ROW_B));
#pragma unroll
        for (int p = 0; p < 2; p++)    ldsm4(bf[0][p], bs + b_frag + p * (16 * ROW_B));
    }

    for (int kt = 0; kt < NT; kt++) {
        const int s = kt & (STAGES - 1);
        const uint32_t as = sb + s * STAGE_B;
        const uint32_t bs = as + A_STAGE_B;

        // RESIDENCY INVARIANT: tiles <= kt+1 must be complete before fragment
        // prefetch below. Newest committed group is tile min(kt+2, NT-1), so
        // allowed-outstanding = 1 only while kt+3 <= NT; 0 in the tail.
        if (kt + 3 <= NT) {
            asm volatile("cp.async.wait_group 1;" ::: "memory");
        } else {
            asm volatile("cp.async.wait_group 0;" ::: "memory");
        }
        __syncthreads();

        if (kt + 3 < NT) stage_tile(kt + 3);

        // prefetch ks=1 frags of this tile
#pragma unroll
        for (int mt = 0; mt < 2; mt++) ldsm4(af[1][mt], as + a_frag + mt * (16 * ROW_B) + 32);
#pragma unroll
        for (int p = 0; p < 2; p++)    ldsm4(bf[1][p], bs + b_frag + p * (16 * ROW_B) + 32);

        // compute ks=0
#pragma unroll
        for (int mt = 0; mt < 2; mt++)
#pragma unroll
            for (int nt = 0; nt < 4; nt++)
                mma_f16(acc[mt][nt], af[0][mt], &bf[0][nt >> 1][(nt & 1) * 2]);

        // prefetch ks=0 frags of NEXT tile (stage kt+1 now guaranteed resident)
        if (kt + 1 < NT) {
            const uint32_t as2 = sb + ((kt + 1) & (STAGES - 1)) * STAGE_B;
            const uint32_t bs2 = as2 + A_STAGE_B;
#pragma unroll
            for (int mt = 0; mt < 2; mt++) ldsm4(af[0][mt], as2 + a_frag + mt * (16 * ROW_B));
#pragma unroll
            for (int p = 0; p < 2; p++)    ldsm4(bf[0][p], bs2 + b_frag + p * (16 * ROW_B));
        }

        // compute ks=1
#pragma unroll
        for (int mt = 0; mt < 2; mt++)
#pragma unroll
            for (int nt = 0; nt < 4; nt++)
                mma_f16(acc[mt][nt], af[1][mt], &bf[1][nt >> 1][(nt & 1) * 2]);
    }

    // Epilogue: out = scale*acc - scale*zero*S + bias
    float Sm[2][2];
#pragma unroll
    for (int mt = 0; mt < 2; mt++) {
        Sm[mt][0] = g_S[bm0 + wm * 32 + mt * 16 + gid];
        Sm[mt][1] = g_S[bm0 + wm * 32 + mt * 16 + gid + 8];
    }
#pragma unroll
    for (int nt = 0; nt < 4; nt++) {
        const int col = bn0 + wn * 32 + nt * 8 + tig * 2;
        const float2 sc = *(const float2*)(scale + col);
        const float2 zr = *(const float2*)(zero + col);
        const float2 bv = *(const float2*)(bias + col);
        const float sz0 = sc.x * zr.x, sz1 = sc.y * zr.y;
#pragma unroll
        for (int mt = 0; mt < 2; mt++) {
            const int row = bm0 + wm * 32 + mt * 16 + gid;
            float2 v0, v1;
            v0.x = sc.x * acc[mt][nt][0] - sz0 * Sm[mt][0] + bv.x;
            v0.y = sc.y * acc[mt][nt][1] - sz1 * Sm[mt][0] + bv.y;
            v1.x = sc.x * acc[mt][nt][2] - sz0 * Sm[mt][1] + bv.x;
            v1.y = sc.y * acc[mt][nt][3] - sz1 * Sm[mt][1] + bv.y;
            *(float2*)(out + (size_t)row * N_TOTAL + col) = v0;
            *(float2*)(out + (size_t)(row + 8) * N_TOTAL + col) = v1;
        }
    }
}

extern "C" void kernel_launch(void* const* d_in, const int* in_sizes, int n_in,
                              void* d_out, int out_size) {
    const float* input  = (const float*)d_in[0];
    const float* weight = (const float*)d_in[1];
    const float* bias   = (const float*)d_in[2];
    const float* scale  = (const float*)d_in[3];
    const float* zero   = (const float*)d_in[4];
    float* out = (float*)d_out;

    prep_kernel<<<N_TOTAL + M_TOTAL, 128>>>(input, weight, scale, zero);

    static bool attr_set = false;
    if (!attr_set) {
        cudaFuncSetAttribute(wq_gemm_kernel, cudaFuncAttributeMaxDynamicSharedMemorySize, SMEM_BYTES);
        attr_set = true;
    }
    dim3 grid(N_TOTAL / BN, M_TOTAL / BM);
    wq_gemm_kernel<<<grid, GEMM_THREADS, SMEM_BYTES>>>(bias, scale, zero, out);
}

// round 11
// speedup vs baseline: 1.2347x; 1.2347x over previous
#include <cuda_runtime.h>
#include <cuda_fp16.h>
#include <cstdint>

// WQuantLinear factorized:
//   q = clip(round(w*(1/scale))+zero, 0, 15)   (exact small int in fp16)
//   out = scale[n]*(sum_k h(a)*q) - scale[n]*zero[n]*S[m] + bias[n],  S[m]=sum_k h(a)
// GEMM: fp16 HMMA m16n8k16, fp32 accum, 4 warps (64x32 warp tiles), BK=64 ->
// only 64 mainloop iterations (halved barrier/wait overhead vs BK=32).

constexpr int M_TOTAL = 256;
constexpr int N_TOTAL = 11008;
constexpr int K_TOTAL = 4096;

constexpr int BM = 128;
constexpr int BN = 64;
constexpr int BK = 64;
constexpr int NT = K_TOTAL / BK;       // 64
constexpr int GEMM_THREADS = 128;      // 4 warps: 2(m) x 2(n), 64x32 warp tiles
constexpr int STAGES = 4;

constexpr int ROW_B = 144;             // 128B data + 16B pad (9x16B; 9 mod 8 = 1 -> conflict-free LDSM)
constexpr int A_STAGE_B = BM * ROW_B;          // 18432
constexpr int B_STAGE_B = BN * ROW_B;          // 9216
constexpr int STAGE_B = A_STAGE_B + B_STAGE_B; // 27648
constexpr int SMEM_BYTES = STAGES * STAGE_B;   // 110592 (2 CTAs/SM fits 228KB)

// ---- device scratch ----
__device__ __half g_Ah[M_TOTAL * K_TOTAL];
__device__ float  g_S[M_TOTAL];
__device__ __half g_Qh[(size_t)N_TOTAL * K_TOTAL];   // 90MB fp16 integer q

__device__ __forceinline__ void mma_f16(float c[4], const uint32_t a[4], const uint32_t b[2]) {
    asm volatile(
        "mma.sync.aligned.m16n8k16.row.col.f32.f16.f16.f32 "
        "{%0,%1,%2,%3}, {%4,%5,%6,%7}, {%8,%9}, {%0,%1,%2,%3};"
        : "+f"(c[0]), "+f"(c[1]), "+f"(c[2]), "+f"(c[3])
        : "r"(a[0]), "r"(a[1]), "r"(a[2]), "r"(a[3]), "r"(b[0]), "r"(b[1]));
}
__device__ __forceinline__ void ldsm4(uint32_t r[4], uint32_t addr) {
    asm volatile("ldmatrix.sync.aligned.m8n8.x4.shared.b16 {%0,%1,%2,%3}, [%4];"
                 : "=r"(r[0]), "=r"(r[1]), "=r"(r[2]), "=r"(r[3]) : "r"(addr));
}
__device__ __forceinline__ void cpasync16(uint32_t dst, const void* src) {
    asm volatile("cp.async.cg.shared.global [%0], [%1], 16;" :: "r"(dst), "l"(src) : "memory");
}
__device__ __forceinline__ uint32_t s2u(const void* p) {
    uint32_t a;
    asm("{ .reg .u64 t; cvta.to.shared.u64 t, %1; cvt.u32.u64 %0, t; }" : "=r"(a) : "l"(p));
    return a;
}

// ---------------- fused prep ----------------
__global__ __launch_bounds__(128) void prep_kernel(const float* __restrict__ A,
                                                   const float* __restrict__ W,
                                                   const float* __restrict__ scale,
                                                   const float* __restrict__ zero) {
    const int tid = threadIdx.x;
    if (blockIdx.x < (unsigned)N_TOTAL) {
        const int row = blockIdx.x;
        const float s = scale[row];
        const float z = zero[row];
        const float r = __fdiv_rn(1.0f, s);
        const float* src = W + (size_t)row * K_TOTAL;
        __half* dst = g_Qh + (size_t)row * K_TOTAL;
#pragma unroll
        for (int i = 0; i < K_TOTAL / (128 * 4); i++) {
            float4 v = *(const float4*)(src + (i * 128 + tid) * 4);
            float q0 = fminf(fmaxf(rintf(__fmul_rn(v.x, r)) + z, 0.0f), 15.0f);
            float q1 = fminf(fmaxf(rintf(__fmul_rn(v.y, r)) + z, 0.0f), 15.0f);
            float q2 = fminf(fmaxf(rintf(__fmul_rn(v.z, r)) + z, 0.0f), 15.0f);
            float q3 = fminf(fmaxf(rintf(__fmul_rn(v.w, r)) + z, 0.0f), 15.0f);
            __half2 p0 = __halves2half2(__float2half_rn(q0), __float2half_rn(q1));
            __half2 p1 = __halves2half2(__float2half_rn(q2), __float2half_rn(q3));
            *(uint2*)(dst + (i * 128 + tid) * 4) =
                make_uint2(*(uint32_t*)&p0, *(uint32_t*)&p1);
        }
    } else {
        const int row = blockIdx.x - N_TOTAL;
        const float* src = A + (size_t)row * K_TOTAL;
        __half* dst = g_Ah + (size_t)row * K_TOTAL;
        float s = 0.0f;
#pragma unroll
        for (int i = 0; i < K_TOTAL / (128 * 4); i++) {
            float4 v = *(const float4*)(src + (i * 128 + tid) * 4);
            __half h0 = __float2half_rn(v.x), h1 = __float2half_rn(v.y);
            __half h2 = __float2half_rn(v.z), h3 = __float2half_rn(v.w);
            __half2 p0 = __halves2half2(h0, h1), p1 = __halves2half2(h2, h3);
            *(uint2*)(dst + (i * 128 + tid) * 4) =
                make_uint2(*(uint32_t*)&p0, *(uint32_t*)&p1);
            s += __half2float(h0) + __half2float(h1) + __half2float(h2) + __half2float(h3);
        }
#pragma unroll
        for (int o = 16; o > 0; o >>= 1) s += __shfl_xor_sync(0xffffffffu, s, o);
        __shared__ float ws[4];
        if ((tid & 31) == 0) ws[tid >> 5] = s;
        __syncthreads();
        if (tid == 0) g_S[row] = ws[0] + ws[1] + ws[2] + ws[3];
    }
}

// ---------------- GEMM ----------------
__global__ __launch_bounds__(GEMM_THREADS, 2)
void wq_gemm_kernel(const float* __restrict__ bias,
                    const float* __restrict__ scale,
                    const float* __restrict__ zero,
                    float* __restrict__ out)
{
    extern __shared__ char smem[];
    const uint32_t sb = s2u(smem);
    const int tid  = threadIdx.x;
    const int wid  = tid >> 5;
    const int lane = tid & 31;
    const int gid  = lane >> 2;
    const int tig  = lane & 3;
    const int wm   = wid & 1;        // 2 m-slabs of 64
    const int wn   = wid >> 1;       // 2 n-slabs of 32
    const int bn0 = blockIdx.x * BN;
    const int bm0 = blockIdx.y * BM;

    const __half* gA = g_Ah + (size_t)bm0 * K_TOTAL;
    const __half* gQ = g_Qh + (size_t)bn0 * K_TOTAL;

    // Staging, BK=64: A = 128 rows x 8 chunks = 1024 (8/thread), B = 64 x 8 = 512 (4/thread)
    const int st_row = tid >> 3;     // 0..15
    const int st_c16 = tid & 7;      // 16B column within 128B row

    auto stage_tile = [&](int kt) {
        const int s = kt & (STAGES - 1);
        const uint32_t as = sb + s * STAGE_B;
        const uint32_t bs = as + A_STAGE_B;
        const int k0 = kt * BK;
#pragma unroll
        for (int j = 0; j < 8; j++) {
            const int row = st_row + 16 * j;
            cpasync16(as + row * ROW_B + st_c16 * 16,
                      gA + (size_t)row * K_TOTAL + k0 + st_c16 * 8);
        }
#pragma unroll
        for (int j = 0; j < 4; j++) {
            const int row = st_row + 16 * j;
            cpasync16(bs + row * ROW_B + st_c16 * 16,
                      gQ + (size_t)row * K_TOTAL + k0 + st_c16 * 8);
        }
        asm volatile("cp.async.commit_group;" ::: "memory");
    };

    stage_tile(0);
    stage_tile(1);
    stage_tile(2);

    // per-lane ldmatrix offsets within a stage (ks*32 byte offset added at use)
    const uint32_t a_frag = (uint32_t)((wm * 64 + (lane & 15)) * ROW_B + (lane >> 4) * 16);
    const uint32_t b_frag = (uint32_t)((wn * 32 + (lane & 7) + ((lane & 16) ? 8 : 0)) * ROW_B
                                       + ((lane & 8) ? 16 : 0));

    float acc[4][4][4];
#pragma unroll
    for (int mt = 0; mt < 4; mt++)
#pragma unroll
        for (int nt = 0; nt < 4; nt++)
#pragma unroll
            for (int i = 0; i < 4; i++) acc[mt][nt][i] = 0.0f;

    uint32_t af[2][4][4];
    uint32_t bf[2][2][4];

    asm volatile("cp.async.wait_group 2;" ::: "memory");
    __syncthreads();
    {   // preload (tile 0, ks 0) -> buf 0
        const uint32_t as = sb, bs = sb + A_STAGE_B;
#pragma unroll
        for (int mt = 0; mt < 4; mt++) ldsm4(af[0][mt], as + a_frag + mt * (16 * ROW_B));
#pragma unroll
        for (int p = 0; p < 2; p++)    ldsm4(bf[0][p], bs + b_frag + p * (16 * ROW_B));
    }

    for (int kt = 0; kt < NT; kt++) {
        const int s = kt & (STAGES - 1);
        const uint32_t as = sb + s * STAGE_B;
        const uint32_t bs = as + A_STAGE_B;

        // RESIDENCY INVARIANT: tiles <= kt+1 must be complete after this wait.
        if (kt + 3 <= NT) {
            asm volatile("cp.async.wait_group 1;" ::: "memory");
        } else {
            asm volatile("cp.async.wait_group 0;" ::: "memory");
        }
        __syncthreads();

        if (kt + 3 < NT) stage_tile(kt + 3);

#pragma unroll
        for (int ks = 0; ks < 4; ks++) {
            const int cur = ks & 1;
            const int nxt = cur ^ 1;
            // prefetch next fragment batch (16 HMMAs below cover its latency)
            if (ks < 3) {
#pragma unroll
                for (int mt = 0; mt < 4; mt++)
                    ldsm4(af[nxt][mt], as + a_frag + mt * (16 * ROW_B) + (ks + 1) * 32);
#pragma unroll
                for (int p = 0; p < 2; p++)
                    ldsm4(bf[nxt][p], bs + b_frag + p * (16 * ROW_B) + (ks + 1) * 32);
            } else if (kt + 1 < NT) {
                const uint32_t as2 = sb + ((kt + 1) & (STAGES - 1)) * STAGE_B;
                const uint32_t bs2 = as2 + A_STAGE_B;
#pragma unroll
                for (int mt = 0; mt < 4; mt++) ldsm4(af[nxt][mt], as2 + a_frag + mt * (16 * ROW_B));
#pragma unroll
                for (int p = 0; p < 2; p++)    ldsm4(bf[nxt][p], bs2 + b_frag + p * (16 * ROW_B));
            }
            // compute ks
#pragma unroll
            for (int mt = 0; mt < 4; mt++)
#pragma unroll
                for (int nt = 0; nt < 4; nt++)
                    mma_f16(acc[mt][nt], af[cur][mt], &bf[cur][nt >> 1][(nt & 1) * 2]);
        }
    }

    // Epilogue: out = scale*acc - scale*zero*S + bias
    float Sm[4][2];
#pragma unroll
    for (int mt = 0; mt < 4; mt++) {
        Sm[mt][0] = g_S[bm0 + wm * 64 + mt * 16 + gid];
        Sm[mt][1] = g_S[bm0 + wm * 64 + mt * 16 + gid + 8];
    }
#pragma unroll
    for (int nt = 0; nt < 4; nt++) {
        const int col = bn0 + wn * 32 + nt * 8 + tig * 2;
        const float2 sc = *(const float2*)(scale + col);
        const float2 zr = *(const float2*)(zero + col);
        const float2 bv = *(const float2*)(bias + col);
        const float sz0 = sc.x * zr.x, sz1 = sc.y * zr.y;
#pragma unroll
        for (int mt = 0; mt < 4; mt++) {
            const int row = bm0 + wm * 64 + mt * 16 + gid;
            float2 v0, v1;
            v0.x = sc.x * acc[mt][nt][0] - sz0 * Sm[mt][0] + bv.x;
            v0.y = sc.y * acc[mt][nt][1] - sz1 * Sm[mt][0] + bv.y;
            v1.x = sc.x * acc[mt][nt][2] - sz0 * Sm[mt][1] + bv.x;
            v1.y = sc.y * acc[mt][nt][3] - sz1 * Sm[mt][1] + bv.y;
            *(float2*)(out + (size_t)row * N_TOTAL + col) = v0;
            *(float2*)(out + (size_t)(row + 8) * N_TOTAL + col) = v1;
        }
    }
}

extern "C" void kernel_launch(void* const* d_in, const int* in_sizes, int n_in,
                              void* d_out, int out_size) {
    const float* input  = (const float*)d_in[0];
    const float* weight = (const float*)d_in[1];
    const float* bias   = (const float*)d_in[2];
    const float* scale  = (const float*)d_in[3];
    const float* zero   = (const float*)d_in[4];
    float* out = (float*)d_out;

    prep_kernel<<<N_TOTAL + M_TOTAL, 128>>>(input, weight, scale, zero);

    static bool attr_set = false;
    if (!attr_set) {
        cudaFuncSetAttribute(wq_gemm_kernel, cudaFuncAttributeMaxDynamicSharedMemorySize, SMEM_BYTES);
        attr_set = true;
    }
    dim3 grid(N_TOTAL / BN, M_TOTAL / BM);
    wq_gemm_kernel<<<grid, GEMM_THREADS, SMEM_BYTES>>>(bias, scale, zero, out);
}